// round 9
// baseline (speedup 1.0000x reference)
#include <cuda_runtime.h>
#include <cuda_fp16.h>

// ---------------------------------------------------------------------------
// KNNGaussianBlur: out = GaussianBlur_sigma4_radius12(img[0]) with replicate
// padding. (/max ... *max cancels -> no reduction.)
//
// R9: two-pass, fp16 scratch (R8). Single change: vblur VROWS 16 -> 24,
// cutting vertical halo read amplification 2.5x -> 2.0x. Model says vblur is
// L2-bound on halo re-reads (603MB L2 ~= 53us @ ~11TB/s LTS, measured 61.6);
// taller tiles drop L2 to ~502MB, converging with the 44us DRAM floor.
// 4096 % 24 != 0 -> grid.y = 171 and the last tile masks its stores.
// ---------------------------------------------------------------------------

#define H_IMG 4096
#define W_IMG 4096
#define C_IMG 3
#define RADIUS 12

// 100.7 MB fp16 scratch (device global: allocation in kernel_launch is banned).
__device__ __half g_scratch[(size_t)C_IMG * H_IMG * W_IMG];

// 13 unique weights, compile-time constants -> FFMA-imm (rt_SMSP=1).
__device__ constexpr float KW[13] = {
    0.09990835f, 0.09683452f, 0.08816879f, 0.07541476f, 0.06059747f,
    0.04574137f, 0.03243549f, 0.02160670f, 0.01352113f, 0.00794866f,
    0.00438966f, 0.00227733f, 0.00110988f
};

// ------------------------------ Vertical pass ------------------------------
// Thread = one f4 column x VROWS output rows; streams VROWS+24 input rows
// with row clamp (= replicate pad). Store converts to half4 (8B coalesced).
constexpr int VROWS   = 24;                        // 48 rows loaded / 24 out
constexpr int VTILES  = (H_IMG + VROWS - 1) / VROWS;   // 171 (last partial)

__global__ __launch_bounds__(128)
void vblur_kernel(const float4* __restrict__ in) {
    const int W4 = W_IMG / 4;                      // 1024
    int col4 = blockIdx.x * 128 + threadIdx.x;     // 0..1023
    int y0   = blockIdx.y * VROWS;
    int cch  = blockIdx.z;

    const float4* inc  = in + (size_t)cch * ((size_t)H_IMG * W4);
    __half*       outc = g_scratch + (size_t)cch * ((size_t)H_IMG * W_IMG);

    float4 acc[VROWS];
#pragma unroll
    for (int i = 0; i < VROWS; ++i) acc[i] = make_float4(0.f, 0.f, 0.f, 0.f);

#pragma unroll
    for (int rr = 0; rr < VROWS + 2 * RADIUS; ++rr) {
        int row = y0 - RADIUS + rr;
        row = row < 0 ? 0 : (row > H_IMG - 1 ? H_IMG - 1 : row);
        float4 v = __ldg(&inc[(size_t)row * W4 + col4]);
#pragma unroll
        for (int i = 0; i < VROWS; ++i) {
            int d = rr - RADIUS - i;               // compile-time per (rr,i)
            if (d >= -RADIUS && d <= RADIUS) {
                float w = KW[d < 0 ? -d : d];
                acc[i].x = fmaf(v.x, w, acc[i].x);
                acc[i].y = fmaf(v.y, w, acc[i].y);
                acc[i].z = fmaf(v.z, w, acc[i].z);
                acc[i].w = fmaf(v.w, w, acc[i].w);
            }
        }
    }

#pragma unroll
    for (int i = 0; i < VROWS; ++i) {
        if (y0 + i < H_IMG) {                      // mask last partial tile
            __half2 lo = __floats2half2_rn(acc[i].x, acc[i].y);
            __half2 hi = __floats2half2_rn(acc[i].z, acc[i].w);
            uint2 pk = make_uint2(*(unsigned*)&lo, *(unsigned*)&hi);
            *(uint2*)(outc + (size_t)(y0 + i) * W_IMG + 4 * (size_t)col4) = pk;
        }
    }
}

// ----------------------------- Horizontal pass -----------------------------
// Unchanged from R8 (issue-bound at its 25-FFMA/px floor). Block = 256 thr =
// 8 warps = one row; lane owns a half8 slot (8 consecutive px); window = 5
// coalesced 16B loads; OOB slots broadcast the edge pixel (exact replicate
// padding since W = 4096 = 512*8). Streamed convert+FMA, fp32 accumulate.
__global__ __launch_bounds__(256)
void hblur_kernel(float* __restrict__ out) {
    int row  = blockIdx.x;
    int cch  = blockIdx.y;
    int w    = threadIdx.x >> 5;
    int lane = threadIdx.x & 31;

    size_t rbase = ((size_t)cch * H_IMG + row) * W_IMG;
    const __half* inr  = g_scratch + rbase;
    const uint4*  in16 = (const uint4*)inr;        // 512 slots of 8 halves

#pragma unroll
    for (int g = 0; g < 2; ++g) {
        int b8   = 64 * w + 32 * g + lane;         // owned slot 0..511
        int base = 8 * b8;                         // first output px

        float acc[8];
#pragma unroll
        for (int p = 0; p < 8; ++p) acc[p] = 0.f;

#pragma unroll
        for (int j = 0; j < 5; ++j) {
            int s = b8 - 2 + j;
            uint4 q;
            if (s >= 0 && s < W_IMG / 8) {
                q = __ldg(&in16[s]);
            } else {
                __half e = __ldg(&inr[s < 0 ? 0 : W_IMG - 1]);
                unsigned he = (unsigned)__half_as_ushort(e);
                he |= he << 16;
                q = make_uint4(he, he, he, he);
            }
#pragma unroll
            for (int h2i = 0; h2i < 4; ++h2i) {
                unsigned uq = (h2i == 0) ? q.x : (h2i == 1) ? q.y
                            : (h2i == 2) ? q.z : q.w;
                float2 f2 = __half22float2(*(__half2*)&uq);
#pragma unroll
                for (int k = 0; k < 2; ++k) {
                    int m  = 8 * j + 2 * h2i + k;  // 0..39, compile-time
                    float xv = k ? f2.y : f2.x;
#pragma unroll
                    for (int p = 0; p < 8; ++p) {
                        int d = m - 16 - p;        // compile-time tap offset
                        if (d >= -RADIUS && d <= RADIUS)
                            acc[p] = fmaf(xv, KW[d < 0 ? -d : d], acc[p]);
                    }
                }
            }
        }

        float* o = out + rbase + base;
        *(float4*)o       = make_float4(acc[0], acc[1], acc[2], acc[3]);
        *(float4*)(o + 4) = make_float4(acc[4], acc[5], acc[6], acc[7]);
    }
}

// ------------------------------ entry point --------------------------------
extern "C" void kernel_launch(void* const* d_in, const int* in_sizes, int n_in,
                              void* d_out, int out_size) {
    const float* img = (const float*)d_in[0];      // [1,3,4096,4096] fp32
    float* out = (float*)d_out;                    // [3,4096,4096] fp32

    dim3 vgrid(W_IMG / 4 / 128, VTILES, C_IMG);    // (8, 171, 3)
    vblur_kernel<<<vgrid, 128>>>((const float4*)img);

    dim3 hgrid(H_IMG, C_IMG);                      // (4096, 3)
    hblur_kernel<<<hgrid, 256>>>(out);
}